// round 14
// baseline (speedup 1.0000x reference)
#include <cuda_runtime.h>
#include <cuda_bf16.h>
#include <cstdint>
#include <math.h>

typedef __nv_bfloat16 bf16;

// ---------------- problem constants ----------------
#define Bb   8
#define Ls   512
#define Dm   512
#define Hh   8
#define DK_  64
#define DFF_ 2048
#define MROWS (Bb*Ls)   // 4096
#define DD   (Dm*Dm)    // 262144

// ---------------- scratch (device globals; no allocation) ----------------
__device__ float g_x   [MROWS*Dm];
__device__ float g_y   [MROWS*Dm];
__device__ float g_mem [MROWS*Dm];
__device__ float g_tmp [MROWS*Dm];
__device__ float g_tmpd[MROWS*Dm];

__device__ bf16 g_xh[MROWS*Dm],  g_xl[MROWS*Dm];
__device__ bf16 g_yh[MROWS*Dm],  g_yl[MROWS*Dm];
__device__ bf16 g_mh[MROWS*Dm],  g_ml[MROWS*Dm];
__device__ bf16 g_qh[MROWS*Dm],  g_ql[MROWS*Dm];
__device__ bf16 g_kh[MROWS*Dm],  g_kl[MROWS*Dm];
__device__ bf16 g_vh[MROWS*Dm],  g_vl[MROWS*Dm];
__device__ bf16 g_ch[MROWS*Dm],  g_cl[MROWS*Dm];
__device__ bf16 g_h1h[(size_t)MROWS*DFF_], g_h1l[(size_t)MROWS*DFF_];
__device__ bf16 g_q2h[MROWS*Dm], g_q2l[MROWS*Dm];
__device__ bf16 g_k2h[MROWS*Dm], g_k2l[MROWS*Dm];
__device__ bf16 g_v2h[MROWS*Dm], g_v2l[MROWS*Dm];
__device__ bf16 g_c2h[MROWS*Dm], g_c2l[MROWS*Dm];
// per-layer precomputed cross-attention K/V (hi/lo)
__device__ bf16 g_ckh[4][MROWS*Dm], g_ckl[4][MROWS*Dm];
__device__ bf16 g_cvh[4][MROWS*Dm], g_cvl[4][MROWS*Dm];

// pre-split weights
#define WOFF_EA  0
#define WOFF_EF1 (WOFF_EA  + 4*4*DD)
#define WOFF_EF2 (WOFF_EF1 + 4*Dm*DFF_)
#define WOFF_DS  (WOFF_EF2 + 4*Dm*DFF_)
#define WOFF_DC  (WOFF_DS  + 4*4*DD)
#define WOFF_DF1 (WOFF_DC  + 4*4*DD)
#define WOFF_DF2 (WOFF_DF1 + 4*Dm*DFF_)
#define WTOTAL   (WOFF_DF2 + 4*Dm*DFF_)
__device__ bf16 g_whi[WTOTAL];
__device__ bf16 g_wlo[WTOTAL];

// ================= helpers =================
__device__ __forceinline__ uint32_t smem_u32(const void* p) {
    uint32_t a;
    asm("{ .reg .u64 t; cvta.to.shared.u64 t, %1; cvt.u32.u64 %0, t; }" : "=r"(a) : "l"(p));
    return a;
}
__device__ __forceinline__ void ldmA(uint32_t* f, uint32_t addr) {
    asm volatile("ldmatrix.sync.aligned.m8n8.x4.shared.b16 {%0,%1,%2,%3}, [%4];"
                 : "=r"(f[0]), "=r"(f[1]), "=r"(f[2]), "=r"(f[3]) : "r"(addr));
}
__device__ __forceinline__ void ldmBT(uint32_t* f, uint32_t addr) {
    asm volatile("ldmatrix.sync.aligned.m8n8.x4.trans.shared.b16 {%0,%1,%2,%3}, [%4];"
                 : "=r"(f[0]), "=r"(f[1]), "=r"(f[2]), "=r"(f[3]) : "r"(addr));
}
__device__ __forceinline__ void mma16816(float* c, const uint32_t* a, const uint32_t* b) {
    asm volatile("mma.sync.aligned.m16n8k16.row.col.f32.bf16.bf16.f32 "
                 "{%0,%1,%2,%3}, {%4,%5,%6,%7}, {%8,%9}, {%0,%1,%2,%3};"
                 : "+f"(c[0]), "+f"(c[1]), "+f"(c[2]), "+f"(c[3])
                 : "r"(a[0]), "r"(a[1]), "r"(a[2]), "r"(a[3]), "r"(b[0]), "r"(b[1]));
}
__device__ __forceinline__ uint32_t pack_split(float x0, float x1, uint32_t& lo_out) {
    bf16 h0 = __float2bfloat16(x0);
    bf16 h1 = __float2bfloat16(x1);
    bf16 l0 = __float2bfloat16(x0 - __bfloat162float(h0));
    bf16 l1 = __float2bfloat16(x1 - __bfloat162float(h1));
    __nv_bfloat162 hp = {h0, h1}, lp = {l0, l1};
    lo_out = *(uint32_t*)&lp;
    return *(uint32_t*)&hp;
}
__device__ __forceinline__ void cpa16(uint32_t saddr, const void* gaddr) {
    asm volatile("cp.async.ca.shared.global [%0], [%1], 16;" :: "r"(saddr), "l"(gaddr));
}
#define CP_COMMIT() asm volatile("cp.async.commit_group;" ::: "memory")
#define CP_WAIT1()  asm volatile("cp.async.wait_group 1;"  ::: "memory")
#define CP_WAIT0()  asm volatile("cp.async.wait_group 0;"  ::: "memory")

// ---------------- weight split kernel ----------------
__global__ void wsplit(const float* __restrict__ in, bf16* __restrict__ hi,
                       bf16* __restrict__ lo, int n4)
{
    int i = blockIdx.x * blockDim.x + threadIdx.x;
    if (i >= n4) return;
    float4 v = ((const float4*)in)[i];
    uint32_t l0, l1;
    uint32_t h0 = pack_split(v.x, v.y, l0);
    uint32_t h1 = pack_split(v.z, v.w, l1);
    ((uint2*)hi)[i] = make_uint2(h0, h1);
    ((uint2*)lo)[i] = make_uint2(l0, l1);
}

// ===================== cp.async bf16 tensor-core GEMM (templated M) =========
template <int MT> struct GP {
    static constexpr int NST   = (MT == 64) ? 4 : 3;   // M64: 4-slot pair pipeline
    static constexpr int A_LO  = MT * 80;
    static constexpr int B_HI  = 2 * MT * 80;
    static constexpr int B_LO  = B_HI + 32 * 272;
    static constexpr int STAGE = B_LO + 32 * 272;
    static constexpr int SMEM  = NST * STAGE;          // M128: 113664, M64: 110592
    static constexpr int NWM   = MT / 32;
    static constexpr int NWN   = 8 / NWM;
    static constexpr int NJ    = (128 / NWN) / 8;
};

template <int MT>
__global__ void __launch_bounds__(256, 2) gemm_bf(
    const bf16* __restrict__ Ahi, const bf16* __restrict__ Alo,
    const bf16* __restrict__ Whi, const bf16* __restrict__ Wlo,
    const float* __restrict__ bias, float* __restrict__ Cf,
    bf16* __restrict__ Ch0, bf16* __restrict__ Cl0,
    bf16* __restrict__ Ch1, bf16* __restrict__ Cl1,
    bf16* __restrict__ Ch2, bf16* __restrict__ Cl2,
    int K, int Nmat, long long Wstride, int mode, int relu)
{
    constexpr int NST = GP<MT>::NST;
    extern __shared__ char smem[];
    const uint32_t sb = smem_u32(smem);
    const int tid = threadIdx.x;
    const int wid = tid >> 5, lid = tid & 31;
    const int wm = wid % GP<MT>::NWM, wn = wid / GP<MT>::NWM;
    const int m0 = wm * 32, n0 = wn * (128 / GP<MT>::NWN);

    const int nbase = blockIdx.x * 128;
    const int mat = nbase / Nmat;
    const int ncol = nbase - mat * Nmat;
    const bf16* Wph = Whi + (size_t)mat * (size_t)Wstride + ncol;
    const bf16* Wpl = Wlo + (size_t)mat * (size_t)Wstride + ncol;
    const bf16* Aph = Ahi + (size_t)blockIdx.y * MT * (size_t)K;
    const bf16* Apl = Alo + (size_t)blockIdx.y * MT * (size_t)K;

    float acc[2][GP<MT>::NJ][4];
#pragma unroll
    for (int i = 0; i < 2; i++)
#pragma unroll
        for (int j = 0; j < GP<MT>::NJ; j++)
#pragma unroll
            for (int r = 0; r < 4; r++) acc[i][j][r] = 0.f;

    auto loadS = [&](int t) {
        const int k0 = t * 32;
        const uint32_t sbase = sb + (t % NST) * GP<MT>::STAGE;
#pragma unroll
        for (int i = 0; i < MT * 4 / 256; i++) {
            int idx = tid + i * 256;
            int row = idx >> 2, ch = idx & 3;
            size_t go = (size_t)row * K + k0 + ch * 8;
            uint32_t so = row * 80 + ch * 16;
            cpa16(sbase + 0 + so, Aph + go);
            cpa16(sbase + GP<MT>::A_LO + so, Apl + go);
        }
#pragma unroll
        for (int i = 0; i < 2; i++) {
            int idx = tid + i * 256;
            int row = idx >> 4, ch = idx & 15;
            size_t go = (size_t)(k0 + row) * Nmat + ch * 8;
            uint32_t so = row * 272 + ch * 16;
            cpa16(sbase + GP<MT>::B_HI + so, Wph + go);
            cpa16(sbase + GP<MT>::B_LO + so, Wpl + go);
        }
        CP_COMMIT();
    };

    const int lr = (lid & 7) + ((lid >> 3) & 1) * 8;
    const int lc = (lid >> 4) * 8;
    const int T = K / 32;

    // one 32-K stage consumption
    auto consume = [&](int t) {
        const uint32_t stg = sb + (t % NST) * GP<MT>::STAGE;
#pragma unroll
        for (int ks = 0; ks < 2; ks++) {
            uint32_t ah[2][4], al[2][4];
#pragma unroll
            for (int mt = 0; mt < 2; mt++) {
                uint32_t aoff = ((m0 + mt * 16 + lr) * 40 + ks * 16 + lc) * 2;
                ldmA(ah[mt], stg + 0 + aoff);
                ldmA(al[mt], stg + GP<MT>::A_LO + aoff);
            }
#pragma unroll
            for (int ng = 0; ng < GP<MT>::NJ / 2; ng++) {
                uint32_t bh4[4], bl4[4];
                uint32_t boff = ((ks * 16 + lr) * 136 + n0 + ng * 16 + lc) * 2;
                ldmBT(bh4, stg + GP<MT>::B_HI + boff);
                ldmBT(bl4, stg + GP<MT>::B_LO + boff);
#pragma unroll
                for (int mt = 0; mt < 2; mt++)
#pragma unroll
                    for (int jj = 0; jj < 2; jj++) {
                        float* c = acc[mt][ng * 2 + jj];
                        mma16816(c, ah[mt], &bh4[jj * 2]);
                        mma16816(c, ah[mt], &bl4[jj * 2]);
                        mma16816(c, al[mt], &bh4[jj * 2]);
                    }
            }
        }
    };

    if constexpr (MT == 64) {
        // pair-consumption 4-slot pipeline: one barrier per TWO stages (T is even)
        loadS(0); loadS(1);
        for (int t = 0; t < T; t += 2) {
            CP_WAIT0();
            __syncthreads();
            if (t + 2 < T) { loadS(t + 2); loadS(t + 3); }
            consume(t);
            consume(t + 1);
        }
    } else {
        loadS(0); loadS(1);
        for (int t = 0; t < T; t++) {
            CP_WAIT1();
            __syncthreads();
            consume(t);
            if (t + 2 < T) loadS(t + 2); else CP_COMMIT();
        }
    }

    // ---- epilogue ----
    const int g = lid >> 2, tq = lid & 3;
    const int browBase = blockIdx.y * MT + m0;
    bf16* Chm = (mat == 0) ? Ch0 : ((mat == 1) ? Ch1 : Ch2);
    bf16* Clm = (mat == 0) ? Cl0 : ((mat == 1) ? Cl1 : Cl2);
#pragma unroll
    for (int mt = 0; mt < 2; mt++) {
#pragma unroll
        for (int j = 0; j < GP<MT>::NJ; j++) {
            int col = ncol + n0 + j * 8 + tq * 2;
            float b0 = bias[(size_t)mat * Nmat + col];
            float b1 = bias[(size_t)mat * Nmat + col + 1];
#pragma unroll
            for (int h = 0; h < 2; h++) {
                int row = browBase + mt * 16 + g + h * 8;
                float v0 = acc[mt][j][h * 2 + 0] + b0;
                float v1 = acc[mt][j][h * 2 + 1] + b1;
                if (relu) { v0 = fmaxf(v0, 0.f); v1 = fmaxf(v1, 0.f); }
                if (mode == 0) {
                    *(float2*)(Cf + (size_t)row * Nmat + col) = make_float2(v0, v1);
                } else {
                    uint32_t lo, hi = pack_split(v0, v1, lo);
                    size_t off;
                    if (mode == 2) {
                        off = (size_t)row * Nmat + col;
                    } else {
                        int b_ = row >> 9, l_ = row & (Ls - 1);
                        int h_ = col >> 6, dk = col & (DK_ - 1);
                        off = (((size_t)(b_ * Hh + h_)) * Ls + l_) * DK_ + dk;
                    }
                    *(uint32_t*)(Chm + off) = hi;
                    *(uint32_t*)(Clm + off) = lo;
                }
            }
        }
    }
}

// ===== fused flash attention: 128 thr, 64-row q tiles, 1 sync/chunk, occ 3 ==
#define QP 72
#define KV_STG  36864
#define FA_TOTAL (2*KV_STG) // 73728

__global__ void __launch_bounds__(128, 3) flash_kernel(
    const bf16* __restrict__ Qh, const bf16* __restrict__ Ql,
    const bf16* __restrict__ Kh, const bf16* __restrict__ Kl,
    const bf16* __restrict__ Vh, const bf16* __restrict__ Vl,
    bf16* __restrict__ Oh, bf16* __restrict__ Ol, int causal)
{
    extern __shared__ char smem[];
    const uint32_t sb = smem_u32(smem);
    const int tid = threadIdx.x, wid = tid >> 5, lid = tid & 31;
    const int qt = blockIdx.x, bh = blockIdx.y;
    const int b_ = bh >> 3, h_ = bh & 7;
    const bf16* Qph = Qh + ((size_t)bh * Ls + qt * 64) * DK_;
    const bf16* Qpl = Ql + ((size_t)bh * Ls + qt * 64) * DK_;
    const bf16* Kph = Kh + (size_t)bh * Ls * DK_;
    const bf16* Kpl = Kl + (size_t)bh * Ls * DK_;
    const bf16* Vph = Vh + (size_t)bh * Ls * DK_;
    const bf16* Vpl = Vl + (size_t)bh * Ls * DK_;

    // stage Q into slot-0 region (reused for KV after frags are in registers)
#pragma unroll
    for (int i = 0; i < 4; i++) {
        int idx = tid + i * 128;
        int row = idx >> 3, ch = idx & 7;
        size_t go = (size_t)row * DK_ + ch * 8;
        uint32_t so = row * 144 + ch * 16;
        *(uint4*)(smem + 0    + so) = *(const uint4*)(Qph + go);
        *(uint4*)(smem + 9216 + so) = *(const uint4*)(Qpl + go);
    }
    __syncthreads();

    const int lr = (lid & 7) + ((lid >> 3) & 1) * 8;
    const int lc = (lid >> 4) * 8;
    const int g = lid >> 2, tq = lid & 3;
    const int m0 = wid * 16;

    uint32_t qh[4][4], ql[4][4];
#pragma unroll
    for (int ks = 0; ks < 4; ks++) {
        uint32_t off = ((m0 + lr) * QP + ks * 16 + lc) * 2;
        ldmA(qh[ks], sb + 0 + off);
        ldmA(ql[ks], sb + 9216 + off);
    }
    __syncthreads();   // all warps hold Q frags; smem free for KV

    auto loadKV = [&](int kt) {
        const uint32_t sbase = sb + (kt & 1) * KV_STG;
#pragma unroll
        for (int i = 0; i < 4; i++) {
            int idx = tid + i * 128;
            int row = idx >> 3, ch = idx & 7;
            size_t go = (size_t)(kt * 64 + row) * DK_ + ch * 8;
            uint32_t so = row * 144 + ch * 16;
            cpa16(sbase + 0     + so, Kph + go);
            cpa16(sbase + 9216  + so, Kpl + go);
            cpa16(sbase + 18432 + so, Vph + go);
            cpa16(sbase + 27648 + so, Vpl + go);
        }
        CP_COMMIT();
    };

    loadKV(0);

    float acc_o[8][4];
#pragma unroll
    for (int j = 0; j < 8; j++)
#pragma unroll
        for (int r = 0; r < 4; r++) acc_o[j][r] = 0.f;
    float mrow[2] = {-1e30f, -1e30f};
    float lrow[2] = {0.f, 0.f};

    const int nch = causal ? (qt + 1) : 8;
    for (int kt = 0; kt < nch; kt++) {
        CP_WAIT0();
        __syncthreads();                 // single sync per chunk
        if (kt + 1 < nch) loadKV(kt + 1);   // safe: overwrites slot consumed before this barrier
        const uint32_t stg = sb + (kt & 1) * KV_STG;

        float s[8][4];
#pragma unroll
        for (int j = 0; j < 8; j++)
#pragma unroll
            for (int r = 0; r < 4; r++) s[j][r] = 0.f;
#pragma unroll
        for (int ks = 0; ks < 4; ks++) {
#pragma unroll
            for (int ng = 0; ng < 4; ng++) {
                uint32_t kh4[4], kl4[4];
                uint32_t off = ((ng * 16 + lr) * QP + ks * 16 + lc) * 2;
                ldmA(kh4, stg + 0 + off);
                ldmA(kl4, stg + 9216 + off);
                uint32_t b0h[2] = {kh4[0], kh4[2]};
                uint32_t b1h[2] = {kh4[1], kh4[3]};
                uint32_t b0l[2] = {kl4[0], kl4[2]};
                uint32_t b1l[2] = {kl4[1], kl4[3]};
                mma16816(s[ng * 2],     qh[ks], b0h);
                mma16816(s[ng * 2],     ql[ks], b0h);
                mma16816(s[ng * 2],     qh[ks], b0l);
                mma16816(s[ng * 2 + 1], qh[ks], b1h);
                mma16816(s[ng * 2 + 1], ql[ks], b1h);
                mma16816(s[ng * 2 + 1], qh[ks], b1l);
            }
        }

        const bool diag = causal && (kt == qt);
#pragma unroll
        for (int r = 0; r < 2; r++) {
            int grow = qt * 64 + m0 + g + r * 8;
            float mx = -1e30f;
#pragma unroll
            for (int j = 0; j < 8; j++) {
                float v0 = s[j][r * 2] * 0.125f;
                float v1 = s[j][r * 2 + 1] * 0.125f;
                if (diag) {
                    int c0 = kt * 64 + j * 8 + tq * 2;
                    if (c0 > grow) v0 = -1e9f;
                    if (c0 + 1 > grow) v1 = -1e9f;
                }
                s[j][r * 2] = v0;
                s[j][r * 2 + 1] = v1;
                mx = fmaxf(mx, fmaxf(v0, v1));
            }
            mx = fmaxf(mx, __shfl_xor_sync(0xffffffffu, mx, 1));
            mx = fmaxf(mx, __shfl_xor_sync(0xffffffffu, mx, 2));
            float mnew = fmaxf(mrow[r], mx);
            float alpha = __expf(mrow[r] - mnew);
            float sum = 0.f;
#pragma unroll
            for (int j = 0; j < 8; j++) {
                float p0 = __expf(s[j][r * 2] - mnew);
                float p1 = __expf(s[j][r * 2 + 1] - mnew);
                s[j][r * 2] = p0;
                s[j][r * 2 + 1] = p1;
                sum += p0 + p1;
            }
            sum += __shfl_xor_sync(0xffffffffu, sum, 1);
            sum += __shfl_xor_sync(0xffffffffu, sum, 2);
            lrow[r] = lrow[r] * alpha + sum;
            mrow[r] = mnew;
#pragma unroll
            for (int j = 0; j < 8; j++) {
                acc_o[j][r * 2] *= alpha;
                acc_o[j][r * 2 + 1] *= alpha;
            }
        }

#pragma unroll
        for (int c = 0; c < 4; c++) {
            uint32_t ph[4], pl[4];
            ph[0] = pack_split(s[2 * c][0],     s[2 * c][1],     pl[0]);
            ph[1] = pack_split(s[2 * c][2],     s[2 * c][3],     pl[1]);
            ph[2] = pack_split(s[2 * c + 1][0], s[2 * c + 1][1], pl[2]);
            ph[3] = pack_split(s[2 * c + 1][2], s[2 * c + 1][3], pl[3]);
#pragma unroll
            for (int ng = 0; ng < 4; ng++) {
                uint32_t vh4[4], vl4[4];
                uint32_t off = ((c * 16 + lr) * QP + ng * 16 + lc) * 2;
                ldmBT(vh4, stg + 18432 + off);
                ldmBT(vl4, stg + 27648 + off);
#pragma unroll
                for (int jj = 0; jj < 2; jj++) {
                    float* cacc = acc_o[ng * 2 + jj];
                    mma16816(cacc, ph, &vh4[jj * 2]);
                    mma16816(cacc, pl, &vh4[jj * 2]);
                    mma16816(cacc, ph, &vl4[jj * 2]);
                }
            }
        }
    }

#pragma unroll
    for (int r = 0; r < 2; r++) {
        float inv = 1.f / lrow[r];
        int row = qt * 64 + m0 + g + r * 8;
        size_t base = ((size_t)b_ * Ls + row) * Dm + h_ * DK_;
#pragma unroll
        for (int j = 0; j < 8; j++) {
            uint32_t lo, hi = pack_split(acc_o[j][r * 2] * inv, acc_o[j][r * 2 + 1] * inv, lo);
            *(uint32_t*)(Oh + base + j * 8 + tq * 2) = hi;
            *(uint32_t*)(Ol + base + j * 8 + tq * 2) = lo;
        }
    }
}

// ---------------- positional encoding add (f32 + hi/lo) ----------------
__global__ void posenc_add(const float* __restrict__ in, float* __restrict__ out,
                           bf16* __restrict__ oh, bf16* __restrict__ ol)
{
    int p = blockIdx.x * blockDim.x + threadIdx.x;
    if (p >= Bb * Ls * Dm / 2) return;
    int d2 = p & (Dm / 2 - 1);
    int l = (p >> 8) & (Ls - 1);
    float div = expf(-(float)(2 * d2) * (9.210340371976184f / (float)Dm));
    float ang = (float)l * div;
    float v0 = in[2 * p] + __sinf(ang);
    float v1 = in[2 * p + 1] + __cosf(ang);
    *(float2*)(out + 2 * p) = make_float2(v0, v1);
    uint32_t lo, hi = pack_split(v0, v1, lo);
    *(uint32_t*)(oh + 2 * p) = hi;
    *(uint32_t*)(ol + 2 * p) = lo;
}

// ---------------- fused residual + LayerNorm (f32 + hi/lo out) -------------
__global__ void ln_kernel(const float* __restrict__ x, const float* __restrict__ res,
                          const float* __restrict__ g, const float* __restrict__ b,
                          float* __restrict__ outf, bf16* __restrict__ oh,
                          bf16* __restrict__ ol)
{
    __shared__ float ss[4], qq[4];
    size_t row = blockIdx.x;
    int tid = threadIdx.x;
    int wid = tid >> 5, lane = tid & 31;
    float4 v = ((const float4*)(x + row * Dm))[tid];
    if (res) {
        float4 r = ((const float4*)(res + row * Dm))[tid];
        v.x += r.x; v.y += r.y; v.z += r.z; v.w += r.w;
    }
    float s = v.x + v.y + v.z + v.w;
    float q = v.x * v.x + v.y * v.y + v.z * v.z + v.w * v.w;
#pragma unroll
    for (int o = 16; o > 0; o >>= 1) {
        s += __shfl_xor_sync(0xffffffffu, s, o);
        q += __shfl_xor_sync(0xffffffffu, q, o);
    }
    if (lane == 0) { ss[wid] = s; qq[wid] = q; }
    __syncthreads();
    s = ss[0] + ss[1] + ss[2] + ss[3];
    q = qq[0] + qq[1] + qq[2] + qq[3];
    float mu = s * (1.f / Dm);
    float var = q * (1.f / Dm) - mu * mu;
    float rs = rsqrtf(var + 1e-5f);
    float4 gv = ((const float4*)g)[tid];
    float4 bv = ((const float4*)b)[tid];
    float4 o;
    o.x = (v.x - mu) * rs * gv.x + bv.x;
    o.y = (v.y - mu) * rs * gv.y + bv.y;
    o.z = (v.z - mu) * rs * gv.z + bv.z;
    o.w = (v.w - mu) * rs * gv.w + bv.w;
    ((float4*)(outf + row * Dm))[tid] = o;
    if (oh) {
        uint32_t l0, l1;
        uint32_t h0 = pack_split(o.x, o.y, l0);
        uint32_t h1 = pack_split(o.z, o.w, l1);
        *(uint2*)(oh + row * Dm + tid * 4) = make_uint2(h0, h1);
        *(uint2*)(ol + row * Dm + tid * 4) = make_uint2(l0, l1);
    }
}

// ---------------- stream/event setup at load time ----------------
struct SideStream {
    cudaStream_t s1 = nullptr;
    cudaEvent_t evFork = nullptr, evJoin = nullptr, evMem = nullptr;
    cudaEvent_t evKV[4] = {};
    bool ok = false;
    SideStream() {
        if (cudaStreamCreateWithFlags(&s1, cudaStreamNonBlocking) != cudaSuccess) return;
        if (cudaEventCreateWithFlags(&evFork, cudaEventDisableTiming) != cudaSuccess) return;
        if (cudaEventCreateWithFlags(&evJoin, cudaEventDisableTiming) != cudaSuccess) return;
        if (cudaEventCreateWithFlags(&evMem,  cudaEventDisableTiming) != cudaSuccess) return;
        for (int i = 0; i < 4; i++)
            if (cudaEventCreateWithFlags(&evKV[i], cudaEventDisableTiming) != cudaSuccess) return;
        ok = true;
    }
};
static SideStream g_ss;

// ---------------- host orchestration ----------------
static inline void run_gemm(const bf16* Ah, const bf16* Al,
                            const bf16* Wh, const bf16* Wl, const float* bias,
                            float* Cf, bf16* Ch0, bf16* Cl0, bf16* Ch1, bf16* Cl1,
                            bf16* Ch2, bf16* Cl2,
                            int K, int Nmat, long long Wstride, int nTilesX,
                            int mode, int relu, bool mt128, cudaStream_t st = 0)
{
    if (mt128) {
        dim3 grid(nTilesX, MROWS / 128);
        gemm_bf<128><<<grid, 256, GP<128>::SMEM, st>>>(Ah, Al, Wh, Wl, bias, Cf,
                                                       Ch0, Cl0, Ch1, Cl1, Ch2, Cl2,
                                                       K, Nmat, Wstride, mode, relu);
    } else {
        dim3 grid(nTilesX, MROWS / 64);
        gemm_bf<64><<<grid, 256, GP<64>::SMEM, st>>>(Ah, Al, Wh, Wl, bias, Cf,
                                                     Ch0, Cl0, Ch1, Cl1, Ch2, Cl2,
                                                     K, Nmat, Wstride, mode, relu);
    }
}
static inline void run_flash(const bf16* Qh, const bf16* Ql, const bf16* Kh, const bf16* Kl,
                             const bf16* Vh, const bf16* Vl, bf16* Oh, bf16* Ol,
                             int causal, cudaStream_t st = 0)
{
    flash_kernel<<<dim3(8, Bb * Hh), 128, FA_TOTAL, st>>>(Qh, Ql, Kh, Kl, Vh, Vl, Oh, Ol, causal);
}

extern "C" void kernel_launch(void* const* d_in, const int* in_sizes, int n_in,
                              void* d_out, int out_size)
{
    static bool attrSet = false;
    if (!attrSet) {
        cudaFuncSetAttribute(gemm_bf<128>, cudaFuncAttributeMaxDynamicSharedMemorySize, GP<128>::SMEM);
        cudaFuncSetAttribute(gemm_bf<64>,  cudaFuncAttributeMaxDynamicSharedMemorySize, GP<64>::SMEM);
        cudaFuncSetAttribute(flash_kernel, cudaFuncAttributeMaxDynamicSharedMemorySize, FA_TOTAL);
        attrSet = true;
    }

    const float* src        = (const float*)d_in[0];
    const float* tgt        = (const float*)d_in[1];
    const float* enc_attn_W = (const float*)d_in[2];
    const float* enc_attn_b = (const float*)d_in[3];
    const float* enc_ffn_W1 = (const float*)d_in[4];
    const float* enc_ffn_b1 = (const float*)d_in[5];
    const float* enc_ffn_W2 = (const float*)d_in[6];
    const float* enc_ffn_b2 = (const float*)d_in[7];
    const float* enc_ln_g   = (const float*)d_in[8];
    const float* enc_ln_b   = (const float*)d_in[9];
    const float* enc_fng    = (const float*)d_in[10];
    const float* enc_fnb    = (const float*)d_in[11];
    const float* dec_sW     = (const float*)d_in[12];
    const float* dec_sb     = (const float*)d_in[13];
    const float* dec_cW     = (const float*)d_in[14];
    const float* dec_cb     = (const float*)d_in[15];
    const float* dW1        = (const float*)d_in[16];
    const float* db1        = (const float*)d_in[17];
    const float* dW2        = (const float*)d_in[18];
    const float* db2        = (const float*)d_in[19];
    const float* dec_ln_g   = (const float*)d_in[20];
    const float* dec_ln_b   = (const float*)d_in[21];
    const float* dec_fng    = (const float*)d_in[22];
    const float* dec_fnb    = (const float*)d_in[23];
    // d_in[24] = tgt_mask: exact causal tril -> applied analytically.

    float *x, *y, *mem, *tmp, *tmpd;
    cudaGetSymbolAddress((void**)&x,    g_x);
    cudaGetSymbolAddress((void**)&y,    g_y);
    cudaGetSymbolAddress((void**)&mem,  g_mem);
    cudaGetSymbolAddress((void**)&tmp,  g_tmp);
    cudaGetSymbolAddress((void**)&tmpd, g_tmpd);
    bf16 *xh,*xl,*yh,*yl,*mh,*ml,*qh,*ql,*kh,*kl,*vh,*vl,*ch,*cl,*h1h,*h1l,*whi,*wlo;
    bf16 *q2h,*q2l,*k2h,*k2l,*v2h,*v2l,*c2h,*c2l;
    bf16 *ckh,*ckl,*cvh,*cvl;
    cudaGetSymbolAddress((void**)&xh, g_xh);  cudaGetSymbolAddress((void**)&xl, g_xl);
    cudaGetSymbolAddress((void**)&yh, g_yh);  cudaGetSymbolAddress((void**)&yl, g_yl);
    cudaGetSymbolAddress((void**)&mh, g_mh);  cudaGetSymbolAddress((void**)&ml, g_ml);
    cudaGetSymbolAddress((void**)&qh, g_qh);  cudaGetSymbolAddress((void**)&ql, g_ql);
    cudaGetSymbolAddress((void**)&kh, g_kh);  cudaGetSymbolAddress((void**)&kl, g_kl);
    cudaGetSymbolAddress((void**)&vh, g_vh);  cudaGetSymbolAddress((void**)&vl, g_vl);
    cudaGetSymbolAddress((void**)&ch, g_ch);  cudaGetSymbolAddress((void**)&cl, g_cl);
    cudaGetSymbolAddress((void**)&h1h, g_h1h); cudaGetSymbolAddress((void**)&h1l, g_h1l);
    cudaGetSymbolAddress((void**)&whi, g_whi); cudaGetSymbolAddress((void**)&wlo, g_wlo);
    cudaGetSymbolAddress((void**)&q2h, g_q2h); cudaGetSymbolAddress((void**)&q2l, g_q2l);
    cudaGetSymbolAddress((void**)&k2h, g_k2h); cudaGetSymbolAddress((void**)&k2l, g_k2l);
    cudaGetSymbolAddress((void**)&v2h, g_v2h); cudaGetSymbolAddress((void**)&v2l, g_v2l);
    cudaGetSymbolAddress((void**)&c2h, g_c2h); cudaGetSymbolAddress((void**)&c2l, g_c2l);
    cudaGetSymbolAddress((void**)&ckh, g_ckh); cudaGetSymbolAddress((void**)&ckl, g_ckl);
    cudaGetSymbolAddress((void**)&cvh, g_cvh); cudaGetSymbolAddress((void**)&cvl, g_cvl);

    const long long DDll = (long long)DD;
    const int nPair = Bb * Ls * Dm / 2;
    const int N4 = 4 * 4 * DD / 4;
    const size_t LSZ = (size_t)MROWS * Dm;

    const bool useSide = g_ss.ok;
    cudaStream_t sB = useSide ? g_ss.s1 : (cudaStream_t)0;

    // ---- fork ----
    if (useSide) {
        cudaEventRecord(g_ss.evFork, 0);
        cudaStreamWaitEvent(sB, g_ss.evFork, 0);
    }

    // ===== stream B: decoder-independent prefix =====
    wsplit<<<N4 / 256, 256, 0, sB>>>(dec_sW, whi + WOFF_DS,  wlo + WOFF_DS,  N4);
    posenc_add<<<nPair / 256, 256, 0, sB>>>(tgt, y, yh, yl);
    {
        const bf16* Wh = whi + WOFF_DS;
        const bf16* Wl = wlo + WOFF_DS;
        run_gemm(yh, yl, Wh, Wl, dec_sb, 0, q2h, q2l, k2h, k2l, v2h, v2l,
                 Dm, Dm, DDll, 12, 1, 0, true, sB);
        run_flash(q2h, q2l, k2h, k2l, v2h, v2l, c2h, c2l, 1, sB);
        run_gemm(c2h, c2l, Wh + 3 * DD, Wl + 3 * DD, dec_sb + 3 * Dm, tmpd,
                 0, 0, 0, 0, 0, 0, Dm, Dm, 0, 4, 0, 0, false, sB);
        ln_kernel<<<MROWS, 128, 0, sB>>>(y, tmpd, dec_ln_g, dec_ln_b, y, yh, yl);
    }
    wsplit<<<N4 / 256, 256, 0, sB>>>(dec_cW, whi + WOFF_DC,  wlo + WOFF_DC,  N4);
    wsplit<<<N4 / 256, 256, 0, sB>>>(dW1,    whi + WOFF_DF1, wlo + WOFF_DF1, N4);
    wsplit<<<N4 / 256, 256, 0, sB>>>(dW2,    whi + WOFF_DF2, wlo + WOFF_DF2, N4);
    if (useSide) cudaEventRecord(g_ss.evJoin, sB);

    // ===== stream A (default): encoder =====
    wsplit<<<N4 / 256, 256>>>(enc_attn_W, whi + WOFF_EA,  wlo + WOFF_EA,  N4);
    wsplit<<<N4 / 256, 256>>>(enc_ffn_W1, whi + WOFF_EF1, wlo + WOFF_EF1, N4);
    wsplit<<<N4 / 256, 256>>>(enc_ffn_W2, whi + WOFF_EF2, wlo + WOFF_EF2, N4);
    posenc_add<<<nPair / 256, 256>>>(src, x, xh, xl);
    for (int l = 0; l < 4; l++) {
        const bf16* Wh = whi + WOFF_EA + (size_t)l * 4 * DD;
        const bf16* Wl = wlo + WOFF_EA + (size_t)l * 4 * DD;
        const float* bb = enc_attn_b + (size_t)l * 4 * Dm;
        run_gemm(xh, xl, Wh, Wl, bb, 0, qh, ql, kh, kl, vh, vl,
                 Dm, Dm, DDll, 12, 1, 0, true);
        run_flash(qh, ql, kh, kl, vh, vl, ch, cl, 0);
        run_gemm(ch, cl, Wh + 3 * DD, Wl + 3 * DD, bb + 3 * Dm, tmp,
                 0, 0, 0, 0, 0, 0, Dm, Dm, 0, 4, 0, 0, false);
        ln_kernel<<<MROWS, 128>>>(x, tmp, enc_ln_g + (size_t)(l * 2) * Dm,
                                  enc_ln_b + (size_t)(l * 2) * Dm, x, xh, xl);
        run_gemm(xh, xl, whi + WOFF_EF1 + (size_t)l * Dm * DFF_,
                 wlo + WOFF_EF1 + (size_t)l * Dm * DFF_, enc_ffn_b1 + (size_t)l * DFF_,
                 0, h1h, h1l, 0, 0, 0, 0, Dm, DFF_, 0, 16, 2, 1, true);
        run_gemm(h1h, h1l, whi + WOFF_EF2 + (size_t)l * DFF_ * Dm,
                 wlo + WOFF_EF2 + (size_t)l * DFF_ * Dm, enc_ffn_b2 + (size_t)l * Dm,
                 tmp, 0, 0, 0, 0, 0, 0, DFF_, Dm, 0, 4, 0, 0, false);
        ln_kernel<<<MROWS, 128>>>(x, tmp, enc_ln_g + (size_t)(l * 2 + 1) * Dm,
                                  enc_ln_b + (size_t)(l * 2 + 1) * Dm, x, xh, xl);
    }
    ln_kernel<<<MROWS, 128>>>(x, nullptr, enc_fng, enc_fnb, mem, mh, ml);

    // ===== precompute ALL cross-attn K/V on stream B (overlaps decoder) =====
    if (useSide) {
        cudaEventRecord(g_ss.evMem, 0);
        cudaStreamWaitEvent(sB, g_ss.evMem, 0);
        for (int l = 0; l < 4; l++) {
            const bf16* Wh = whi + WOFF_DC + (size_t)l * 4 * DD;
            const bf16* Wl = wlo + WOFF_DC + (size_t)l * 4 * DD;
            const float* bb = dec_cb + (size_t)l * 4 * Dm;
            run_gemm(mh, ml, Wh + DD, Wl + DD, bb + Dm, 0,
                     ckh + l * LSZ, ckl + l * LSZ, cvh + l * LSZ, cvl + l * LSZ, 0, 0,
                     Dm, Dm, DDll, 8, 1, 0, true, sB);
            cudaEventRecord(g_ss.evKV[l], sB);
        }
    }

    // ---- join (decoder prefix) ----
    if (useSide) cudaStreamWaitEvent(0, g_ss.evJoin, 0);

    // ===== decoder (layer 0 self-attn precomputed on stream B) =====
    for (int l = 0; l < 4; l++) {
        if (l > 0) {
            const bf16* Wh = whi + WOFF_DS + (size_t)l * 4 * DD;
            const bf16* Wl = wlo + WOFF_DS + (size_t)l * 4 * DD;
            const float* bb = dec_sb + (size_t)l * 4 * Dm;
            run_gemm(yh, yl, Wh, Wl, bb, 0, qh, ql, kh, kl, vh, vl,
                     Dm, Dm, DDll, 12, 1, 0, true);
            run_flash(qh, ql, kh, kl, vh, vl, ch, cl, 1);
            run_gemm(ch, cl, Wh + 3 * DD, Wl + 3 * DD, bb + 3 * Dm, tmp,
                     0, 0, 0, 0, 0, 0, Dm, Dm, 0, 4, 0, 0, false);
            ln_kernel<<<MROWS, 128>>>(y, tmp, dec_ln_g + (size_t)(l * 3) * Dm,
                                      dec_ln_b + (size_t)(l * 3) * Dm, y, yh, yl);
        }
        // cross-attention
        {
            const bf16* Wh = whi + WOFF_DC + (size_t)l * 4 * DD;
            const bf16* Wl = wlo + WOFF_DC + (size_t)l * 4 * DD;
            const float* bb = dec_cb + (size_t)l * 4 * Dm;
            run_gemm(yh, yl, Wh, Wl, bb, 0, qh, ql, 0, 0, 0, 0,
                     Dm, Dm, 0, 4, 1, 0, false);
            const bf16 *Kh2, *Kl2, *Vh2, *Vl2;
            if (useSide) {
                cudaStreamWaitEvent(0, g_ss.evKV[l], 0);
                Kh2 = ckh + l * LSZ; Kl2 = ckl + l * LSZ;
                Vh2 = cvh + l * LSZ; Vl2 = cvl + l * LSZ;
            } else {
                run_gemm(mh, ml, Wh + DD, Wl + DD, bb + Dm, 0, kh, kl, vh, vl, 0, 0,
                         Dm, Dm, DDll, 8, 1, 0, true);
                Kh2 = kh; Kl2 = kl; Vh2 = vh; Vl2 = vl;
            }
            run_flash(qh, ql, Kh2, Kl2, Vh2, Vl2, ch, cl, 0);
            run_gemm(ch, cl, Wh + 3 * DD, Wl + 3 * DD, bb + 3 * Dm, tmp,
                     0, 0, 0, 0, 0, 0, Dm, Dm, 0, 4, 0, 0, false);
            ln_kernel<<<MROWS, 128>>>(y, tmp, dec_ln_g + (size_t)(l * 3 + 1) * Dm,
                                      dec_ln_b + (size_t)(l * 3 + 1) * Dm, y, yh, yl);
        }
        // FFN
        run_gemm(yh, yl, whi + WOFF_DF1 + (size_t)l * Dm * DFF_,
                 wlo + WOFF_DF1 + (size_t)l * Dm * DFF_, db1 + (size_t)l * DFF_,
                 0, h1h, h1l, 0, 0, 0, 0, Dm, DFF_, 0, 16, 2, 1, true);
        run_gemm(h1h, h1l, whi + WOFF_DF2 + (size_t)l * DFF_ * Dm,
                 wlo + WOFF_DF2 + (size_t)l * DFF_ * Dm, db2 + (size_t)l * Dm,
                 tmp, 0, 0, 0, 0, 0, 0, DFF_, Dm, 0, 4, 0, 0, false);
        ln_kernel<<<MROWS, 128>>>(y, tmp, dec_ln_g + (size_t)(l * 3 + 2) * Dm,
                                  dec_ln_b + (size_t)(l * 3 + 2) * Dm, y, yh, yl);
    }
    ln_kernel<<<MROWS, 128>>>(y, nullptr, dec_fng, dec_fnb, (float*)d_out, 0, 0);
}

// round 15
// speedup vs baseline: 1.0682x; 1.0682x over previous
#include <cuda_runtime.h>
#include <cuda_bf16.h>
#include <cstdint>
#include <math.h>

typedef __nv_bfloat16 bf16;

// ---------------- problem constants ----------------
#define Bb   8
#define Ls   512
#define Dm   512
#define Hh   8
#define DK_  64
#define DFF_ 2048
#define MROWS (Bb*Ls)   // 4096
#define DD   (Dm*Dm)    // 262144

// ---------------- scratch (device globals; no allocation) ----------------
__device__ float g_x   [MROWS*Dm];
__device__ float g_y   [MROWS*Dm];
__device__ float g_mem [MROWS*Dm];
__device__ float g_tmp [MROWS*Dm];
__device__ float g_tmpd[MROWS*Dm];

__device__ bf16 g_xh[MROWS*Dm],  g_xl[MROWS*Dm];
__device__ bf16 g_yh[MROWS*Dm],  g_yl[MROWS*Dm];
__device__ bf16 g_mh[MROWS*Dm],  g_ml[MROWS*Dm];
__device__ bf16 g_qh[MROWS*Dm],  g_ql[MROWS*Dm];
__device__ bf16 g_kh[MROWS*Dm],  g_kl[MROWS*Dm];
__device__ bf16 g_vh[MROWS*Dm],  g_vl[MROWS*Dm];
__device__ bf16 g_ch[MROWS*Dm],  g_cl[MROWS*Dm];
__device__ bf16 g_h1h[(size_t)MROWS*DFF_], g_h1l[(size_t)MROWS*DFF_];
__device__ bf16 g_q2h[MROWS*Dm], g_q2l[MROWS*Dm];
__device__ bf16 g_k2h[MROWS*Dm], g_k2l[MROWS*Dm];
__device__ bf16 g_v2h[MROWS*Dm], g_v2l[MROWS*Dm];
__device__ bf16 g_c2h[MROWS*Dm], g_c2l[MROWS*Dm];

// pre-split weights
#define WOFF_EA  0
#define WOFF_EF1 (WOFF_EA  + 4*4*DD)
#define WOFF_EF2 (WOFF_EF1 + 4*Dm*DFF_)
#define WOFF_DS  (WOFF_EF2 + 4*Dm*DFF_)
#define WOFF_DC  (WOFF_DS  + 4*4*DD)
#define WOFF_DF1 (WOFF_DC  + 4*4*DD)
#define WOFF_DF2 (WOFF_DF1 + 4*Dm*DFF_)
#define WTOTAL   (WOFF_DF2 + 4*Dm*DFF_)
__device__ bf16 g_whi[WTOTAL];
__device__ bf16 g_wlo[WTOTAL];

// ================= helpers =================
__device__ __forceinline__ uint32_t smem_u32(const void* p) {
    uint32_t a;
    asm("{ .reg .u64 t; cvta.to.shared.u64 t, %1; cvt.u32.u64 %0, t; }" : "=r"(a) : "l"(p));
    return a;
}
__device__ __forceinline__ void ldmA(uint32_t* f, uint32_t addr) {
    asm volatile("ldmatrix.sync.aligned.m8n8.x4.shared.b16 {%0,%1,%2,%3}, [%4];"
                 : "=r"(f[0]), "=r"(f[1]), "=r"(f[2]), "=r"(f[3]) : "r"(addr));
}
__device__ __forceinline__ void ldmBT(uint32_t* f, uint32_t addr) {
    asm volatile("ldmatrix.sync.aligned.m8n8.x4.trans.shared.b16 {%0,%1,%2,%3}, [%4];"
                 : "=r"(f[0]), "=r"(f[1]), "=r"(f[2]), "=r"(f[3]) : "r"(addr));
}
__device__ __forceinline__ void mma16816(float* c, const uint32_t* a, const uint32_t* b) {
    asm volatile("mma.sync.aligned.m16n8k16.row.col.f32.bf16.bf16.f32 "
                 "{%0,%1,%2,%3}, {%4,%5,%6,%7}, {%8,%9}, {%0,%1,%2,%3};"
                 : "+f"(c[0]), "+f"(c[1]), "+f"(c[2]), "+f"(c[3])
                 : "r"(a[0]), "r"(a[1]), "r"(a[2]), "r"(a[3]), "r"(b[0]), "r"(b[1]));
}
__device__ __forceinline__ uint32_t pack_split(float x0, float x1, uint32_t& lo_out) {
    bf16 h0 = __float2bfloat16(x0);
    bf16 h1 = __float2bfloat16(x1);
    bf16 l0 = __float2bfloat16(x0 - __bfloat162float(h0));
    bf16 l1 = __float2bfloat16(x1 - __bfloat162float(h1));
    __nv_bfloat162 hp = {h0, h1}, lp = {l0, l1};
    lo_out = *(uint32_t*)&lp;
    return *(uint32_t*)&hp;
}
__device__ __forceinline__ void cpa16(uint32_t saddr, const void* gaddr) {
    asm volatile("cp.async.ca.shared.global [%0], [%1], 16;" :: "r"(saddr), "l"(gaddr));
}
#define CP_COMMIT() asm volatile("cp.async.commit_group;" ::: "memory")
#define CP_WAIT1()  asm volatile("cp.async.wait_group 1;"  ::: "memory")
#define CP_WAIT0()  asm volatile("cp.async.wait_group 0;"  ::: "memory")

// ---------------- weight split kernel ----------------
__global__ void wsplit(const float* __restrict__ in, bf16* __restrict__ hi,
                       bf16* __restrict__ lo, int n4)
{
    int i = blockIdx.x * blockDim.x + threadIdx.x;
    if (i >= n4) return;
    float4 v = ((const float4*)in)[i];
    uint32_t l0, l1;
    uint32_t h0 = pack_split(v.x, v.y, l0);
    uint32_t h1 = pack_split(v.z, v.w, l1);
    ((uint2*)hi)[i] = make_uint2(h0, h1);
    ((uint2*)lo)[i] = make_uint2(l0, l1);
}

// ===================== cp.async bf16 tensor-core GEMM (templated M) =========
#define NSTAGE 3
template <int MT> struct GP {
    static constexpr int A_LO  = MT * 80;
    static constexpr int B_HI  = 2 * MT * 80;
    static constexpr int B_LO  = B_HI + 32 * 272;
    static constexpr int STAGE = B_LO + 32 * 272;
    static constexpr int SMEM  = NSTAGE * STAGE;
    static constexpr int NWM   = MT / 32;
    static constexpr int NWN   = 8 / NWM;
    static constexpr int NJ    = (128 / NWN) / 8;
};

template <int MT>
__global__ void __launch_bounds__(256, 2) gemm_bf(
    const bf16* __restrict__ Ahi, const bf16* __restrict__ Alo,
    const bf16* __restrict__ Whi, const bf16* __restrict__ Wlo,
    const float* __restrict__ bias, float* __restrict__ Cf,
    bf16* __restrict__ Ch0, bf16* __restrict__ Cl0,
    bf16* __restrict__ Ch1, bf16* __restrict__ Cl1,
    bf16* __restrict__ Ch2, bf16* __restrict__ Cl2,
    int K, int Nmat, long long Wstride, int mode, int relu)
{
    extern __shared__ char smem[];
    const uint32_t sb = smem_u32(smem);
    const int tid = threadIdx.x;
    const int wid = tid >> 5, lid = tid & 31;
    const int wm = wid % GP<MT>::NWM, wn = wid / GP<MT>::NWM;
    const int m0 = wm * 32, n0 = wn * (128 / GP<MT>::NWN);

    const int nbase = blockIdx.x * 128;
    const int mat = nbase / Nmat;
    const int ncol = nbase - mat * Nmat;
    const bf16* Wph = Whi + (size_t)mat * (size_t)Wstride + ncol;
    const bf16* Wpl = Wlo + (size_t)mat * (size_t)Wstride + ncol;
    const bf16* Aph = Ahi + (size_t)blockIdx.y * MT * (size_t)K;
    const bf16* Apl = Alo + (size_t)blockIdx.y * MT * (size_t)K;

    float acc[2][GP<MT>::NJ][4];
#pragma unroll
    for (int i = 0; i < 2; i++)
#pragma unroll
        for (int j = 0; j < GP<MT>::NJ; j++)
#pragma unroll
            for (int r = 0; r < 4; r++) acc[i][j][r] = 0.f;

    auto loadS = [&](int t) {
        const int k0 = t * 32;
        const uint32_t sbase = sb + (t % NSTAGE) * GP<MT>::STAGE;
#pragma unroll
        for (int i = 0; i < MT * 4 / 256; i++) {
            int idx = tid + i * 256;
            int row = idx >> 2, ch = idx & 3;
            size_t go = (size_t)row * K + k0 + ch * 8;
            uint32_t so = row * 80 + ch * 16;
            cpa16(sbase + 0 + so, Aph + go);
            cpa16(sbase + GP<MT>::A_LO + so, Apl + go);
        }
#pragma unroll
        for (int i = 0; i < 2; i++) {
            int idx = tid + i * 256;
            int row = idx >> 4, ch = idx & 15;
            size_t go = (size_t)(k0 + row) * Nmat + ch * 8;
            uint32_t so = row * 272 + ch * 16;
            cpa16(sbase + GP<MT>::B_HI + so, Wph + go);
            cpa16(sbase + GP<MT>::B_LO + so, Wpl + go);
        }
        CP_COMMIT();
    };

    const int T = K / 32;
    loadS(0);
    loadS(1);

    const int lr = (lid & 7) + ((lid >> 3) & 1) * 8;
    const int lc = (lid >> 4) * 8;

    for (int t = 0; t < T; t++) {
        CP_WAIT1();
        __syncthreads();
        const uint32_t stg = sb + (t % NSTAGE) * GP<MT>::STAGE;
#pragma unroll
        for (int ks = 0; ks < 2; ks++) {
            uint32_t ah[2][4], al[2][4];
#pragma unroll
            for (int mt = 0; mt < 2; mt++) {
                uint32_t aoff = ((m0 + mt * 16 + lr) * 40 + ks * 16 + lc) * 2;
                ldmA(ah[mt], stg + 0 + aoff);
                ldmA(al[mt], stg + GP<MT>::A_LO + aoff);
            }
#pragma unroll
            for (int ng = 0; ng < GP<MT>::NJ / 2; ng++) {
                uint32_t bh4[4], bl4[4];
                uint32_t boff = ((ks * 16 + lr) * 136 + n0 + ng * 16 + lc) * 2;
                ldmBT(bh4, stg + GP<MT>::B_HI + boff);
                ldmBT(bl4, stg + GP<MT>::B_LO + boff);
#pragma unroll
                for (int mt = 0; mt < 2; mt++)
#pragma unroll
                    for (int jj = 0; jj < 2; jj++) {
                        float* c = acc[mt][ng * 2 + jj];
                        mma16816(c, ah[mt], &bh4[jj * 2]);
                        mma16816(c, ah[mt], &bl4[jj * 2]);
                        mma16816(c, al[mt], &bh4[jj * 2]);
                    }
            }
        }
        if (t + 2 < T) loadS(t + 2); else CP_COMMIT();
    }

    // ---- epilogue ----
    const int g = lid >> 2, tq = lid & 3;
    const int browBase = blockIdx.y * MT + m0;
    bf16* Chm = (mat == 0) ? Ch0 : ((mat == 1) ? Ch1 : Ch2);
    bf16* Clm = (mat == 0) ? Cl0 : ((mat == 1) ? Cl1 : Cl2);
#pragma unroll
    for (int mt = 0; mt < 2; mt++) {
#pragma unroll
        for (int j = 0; j < GP<MT>::NJ; j++) {
            int col = ncol + n0 + j * 8 + tq * 2;
            float b0 = bias[(size_t)mat * Nmat + col];
            float b1 = bias[(size_t)mat * Nmat + col + 1];
#pragma unroll
            for (int h = 0; h < 2; h++) {
                int row = browBase + mt * 16 + g + h * 8;
                float v0 = acc[mt][j][h * 2 + 0] + b0;
                float v1 = acc[mt][j][h * 2 + 1] + b1;
                if (relu) { v0 = fmaxf(v0, 0.f); v1 = fmaxf(v1, 0.f); }
                if (mode == 0) {
                    *(float2*)(Cf + (size_t)row * Nmat + col) = make_float2(v0, v1);
                } else {
                    uint32_t lo, hi = pack_split(v0, v1, lo);
                    size_t off;
                    if (mode == 2) {
                        off = (size_t)row * Nmat + col;
                    } else {
                        int b_ = row >> 9, l_ = row & (Ls - 1);
                        int h_ = col >> 6, dk = col & (DK_ - 1);
                        off = (((size_t)(b_ * Hh + h_)) * Ls + l_) * DK_ + dk;
                    }
                    *(uint32_t*)(Chm + off) = hi;
                    *(uint32_t*)(Clm + off) = lo;
                }
            }
        }
    }
}

// ============ fused flash attention: 128 threads, 64-row q tiles, occ 2 =====
#define QP 72
#define FA_Q_HI 0
#define FA_Q_LO 9216
#define FA_KV   18432
#define KV_STG  36864       // per-stage: Khi 0, Klo 9216, Vhi 18432, Vlo 27648
#define FA_TOTAL (FA_KV + 2*KV_STG)   // 92160

__global__ void __launch_bounds__(128, 2) flash_kernel(
    const bf16* __restrict__ Qh, const bf16* __restrict__ Ql,
    const bf16* __restrict__ Kh, const bf16* __restrict__ Kl,
    const bf16* __restrict__ Vh, const bf16* __restrict__ Vl,
    bf16* __restrict__ Oh, bf16* __restrict__ Ol, int causal)
{
    extern __shared__ char smem[];
    const uint32_t sb = smem_u32(smem);
    const int tid = threadIdx.x, wid = tid >> 5, lid = tid & 31;
    const int qt = blockIdx.x, bh = blockIdx.y;   // qt: 0..7 (64-row tiles)
    const int b_ = bh >> 3, h_ = bh & 7;
    const bf16* Qph = Qh + ((size_t)bh * Ls + qt * 64) * DK_;
    const bf16* Qpl = Ql + ((size_t)bh * Ls + qt * 64) * DK_;
    const bf16* Kph = Kh + (size_t)bh * Ls * DK_;
    const bf16* Kpl = Kl + (size_t)bh * Ls * DK_;
    const bf16* Vph = Vh + (size_t)bh * Ls * DK_;
    const bf16* Vpl = Vl + (size_t)bh * Ls * DK_;

    auto loadKV = [&](int kt) {
        const uint32_t sbase = sb + FA_KV + (kt & 1) * KV_STG;
#pragma unroll
        for (int i = 0; i < 4; i++) {
            int idx = tid + i * 128;
            int row = idx >> 3, ch = idx & 7;
            size_t go = (size_t)(kt * 64 + row) * DK_ + ch * 8;
            uint32_t so = row * 144 + ch * 16;
            cpa16(sbase + 0     + so, Kph + go);
            cpa16(sbase + 9216  + so, Kpl + go);
            cpa16(sbase + 18432 + so, Vph + go);
            cpa16(sbase + 27648 + so, Vpl + go);
        }
        CP_COMMIT();
    };

    loadKV(0);

    // load Q tile (64 x 64 bf16)
#pragma unroll
    for (int i = 0; i < 4; i++) {
        int idx = tid + i * 128;
        int row = idx >> 3, ch = idx & 7;
        size_t go = (size_t)row * DK_ + ch * 8;
        uint32_t so = row * 144 + ch * 16;
        *(uint4*)(smem + FA_Q_HI + so) = *(const uint4*)(Qph + go);
        *(uint4*)(smem + FA_Q_LO + so) = *(const uint4*)(Qpl + go);
    }
    __syncthreads();

    const int lr = (lid & 7) + ((lid >> 3) & 1) * 8;
    const int lc = (lid >> 4) * 8;
    const int g = lid >> 2, tq = lid & 3;
    const int m0 = wid * 16;

    uint32_t qh[4][4], ql[4][4];
#pragma unroll
    for (int ks = 0; ks < 4; ks++) {
        uint32_t off = ((m0 + lr) * QP + ks * 16 + lc) * 2;
        ldmA(qh[ks], sb + FA_Q_HI + off);
        ldmA(ql[ks], sb + FA_Q_LO + off);
    }

    float acc_o[8][4];
#pragma unroll
    for (int j = 0; j < 8; j++)
#pragma unroll
        for (int r = 0; r < 4; r++) acc_o[j][r] = 0.f;
    float mrow[2] = {-1e30f, -1e30f};
    float lrow[2] = {0.f, 0.f};

    const int nch = causal ? (qt + 1) : 8;
    for (int kt = 0; kt < nch; kt++) {
        if (kt + 1 < nch) { loadKV(kt + 1); CP_WAIT1(); }
        else              { CP_WAIT0(); }
        __syncthreads();
        const uint32_t stg = sb + FA_KV + (kt & 1) * KV_STG;

        float s[8][4];
#pragma unroll
        for (int j = 0; j < 8; j++)
#pragma unroll
            for (int r = 0; r < 4; r++) s[j][r] = 0.f;
#pragma unroll
        for (int ks = 0; ks < 4; ks++) {
#pragma unroll
            for (int ng = 0; ng < 4; ng++) {
                uint32_t kh4[4], kl4[4];
                uint32_t off = ((ng * 16 + lr) * QP + ks * 16 + lc) * 2;
                ldmA(kh4, stg + 0 + off);
                ldmA(kl4, stg + 9216 + off);
                uint32_t b0h[2] = {kh4[0], kh4[2]};
                uint32_t b1h[2] = {kh4[1], kh4[3]};
                uint32_t b0l[2] = {kl4[0], kl4[2]};
                uint32_t b1l[2] = {kl4[1], kl4[3]};
                mma16816(s[ng * 2],     qh[ks], b0h);
                mma16816(s[ng * 2],     ql[ks], b0h);
                mma16816(s[ng * 2],     qh[ks], b0l);
                mma16816(s[ng * 2 + 1], qh[ks], b1h);
                mma16816(s[ng * 2 + 1], ql[ks], b1h);
                mma16816(s[ng * 2 + 1], qh[ks], b1l);
            }
        }

        const bool diag = causal && (kt == qt);
#pragma unroll
        for (int r = 0; r < 2; r++) {
            int grow = qt * 64 + m0 + g + r * 8;
            float mx = -1e30f;
#pragma unroll
            for (int j = 0; j < 8; j++) {
                float v0 = s[j][r * 2] * 0.125f;
                float v1 = s[j][r * 2 + 1] * 0.125f;
                if (diag) {
                    int c0 = kt * 64 + j * 8 + tq * 2;
                    if (c0 > grow) v0 = -1e9f;
                    if (c0 + 1 > grow) v1 = -1e9f;
                }
                s[j][r * 2] = v0;
                s[j][r * 2 + 1] = v1;
                mx = fmaxf(mx, fmaxf(v0, v1));
            }
            mx = fmaxf(mx, __shfl_xor_sync(0xffffffffu, mx, 1));
            mx = fmaxf(mx, __shfl_xor_sync(0xffffffffu, mx, 2));
            float mnew = fmaxf(mrow[r], mx);
            float alpha = __expf(mrow[r] - mnew);
            float sum = 0.f;
#pragma unroll
            for (int j = 0; j < 8; j++) {
                float p0 = __expf(s[j][r * 2] - mnew);
                float p1 = __expf(s[j][r * 2 + 1] - mnew);
                s[j][r * 2] = p0;
                s[j][r * 2 + 1] = p1;
                sum += p0 + p1;
            }
            sum += __shfl_xor_sync(0xffffffffu, sum, 1);
            sum += __shfl_xor_sync(0xffffffffu, sum, 2);
            lrow[r] = lrow[r] * alpha + sum;
            mrow[r] = mnew;
#pragma unroll
            for (int j = 0; j < 8; j++) {
                acc_o[j][r * 2] *= alpha;
                acc_o[j][r * 2 + 1] *= alpha;
            }
        }

#pragma unroll
        for (int c = 0; c < 4; c++) {
            uint32_t ph[4], pl[4];
            ph[0] = pack_split(s[2 * c][0],     s[2 * c][1],     pl[0]);
            ph[1] = pack_split(s[2 * c][2],     s[2 * c][3],     pl[1]);
            ph[2] = pack_split(s[2 * c + 1][0], s[2 * c + 1][1], pl[2]);
            ph[3] = pack_split(s[2 * c + 1][2], s[2 * c + 1][3], pl[3]);
#pragma unroll
            for (int ng = 0; ng < 4; ng++) {
                uint32_t vh4[4], vl4[4];
                uint32_t off = ((c * 16 + lr) * QP + ng * 16 + lc) * 2;
                ldmBT(vh4, stg + 18432 + off);
                ldmBT(vl4, stg + 27648 + off);
#pragma unroll
                for (int jj = 0; jj < 2; jj++) {
                    float* cacc = acc_o[ng * 2 + jj];
                    mma16816(cacc, ph, &vh4[jj * 2]);
                    mma16816(cacc, pl, &vh4[jj * 2]);
                    mma16816(cacc, ph, &vl4[jj * 2]);
                }
            }
        }
        __syncthreads();
    }

#pragma unroll
    for (int r = 0; r < 2; r++) {
        float inv = 1.f / lrow[r];
        int row = qt * 64 + m0 + g + r * 8;
        size_t base = ((size_t)b_ * Ls + row) * Dm + h_ * DK_;
#pragma unroll
        for (int j = 0; j < 8; j++) {
            uint32_t lo, hi = pack_split(acc_o[j][r * 2] * inv, acc_o[j][r * 2 + 1] * inv, lo);
            *(uint32_t*)(Oh + base + j * 8 + tq * 2) = hi;
            *(uint32_t*)(Ol + base + j * 8 + tq * 2) = lo;
        }
    }
}

// ---------------- positional encoding add (f32 + hi/lo) ----------------
__global__ void posenc_add(const float* __restrict__ in, float* __restrict__ out,
                           bf16* __restrict__ oh, bf16* __restrict__ ol)
{
    int p = blockIdx.x * blockDim.x + threadIdx.x;
    if (p >= Bb * Ls * Dm / 2) return;
    int d2 = p & (Dm / 2 - 1);
    int l = (p >> 8) & (Ls - 1);
    float div = expf(-(float)(2 * d2) * (9.210340371976184f / (float)Dm));
    float ang = (float)l * div;
    float v0 = in[2 * p] + __sinf(ang);
    float v1 = in[2 * p + 1] + __cosf(ang);
    *(float2*)(out + 2 * p) = make_float2(v0, v1);
    uint32_t lo, hi = pack_split(v0, v1, lo);
    *(uint32_t*)(oh + 2 * p) = hi;
    *(uint32_t*)(ol + 2 * p) = lo;
}

// ---------------- fused residual + LayerNorm (f32 + hi/lo out) -------------
__global__ void ln_kernel(const float* __restrict__ x, const float* __restrict__ res,
                          const float* __restrict__ g, const float* __restrict__ b,
                          float* __restrict__ outf, bf16* __restrict__ oh,
                          bf16* __restrict__ ol)
{
    __shared__ float ss[4], qq[4];
    size_t row = blockIdx.x;
    int tid = threadIdx.x;            // 128 threads
    int wid = tid >> 5, lane = tid & 31;
    float4 v = ((const float4*)(x + row * Dm))[tid];
    if (res) {
        float4 r = ((const float4*)(res + row * Dm))[tid];
        v.x += r.x; v.y += r.y; v.z += r.z; v.w += r.w;
    }
    float s = v.x + v.y + v.z + v.w;
    float q = v.x * v.x + v.y * v.y + v.z * v.z + v.w * v.w;
#pragma unroll
    for (int o = 16; o > 0; o >>= 1) {
        s += __shfl_xor_sync(0xffffffffu, s, o);
        q += __shfl_xor_sync(0xffffffffu, q, o);
    }
    if (lane == 0) { ss[wid] = s; qq[wid] = q; }
    __syncthreads();
    s = ss[0] + ss[1] + ss[2] + ss[3];
    q = qq[0] + qq[1] + qq[2] + qq[3];
    float mu = s * (1.f / Dm);
    float var = q * (1.f / Dm) - mu * mu;
    float rs = rsqrtf(var + 1e-5f);
    float4 gv = ((const float4*)g)[tid];
    float4 bv = ((const float4*)b)[tid];
    float4 o;
    o.x = (v.x - mu) * rs * gv.x + bv.x;
    o.y = (v.y - mu) * rs * gv.y + bv.y;
    o.z = (v.z - mu) * rs * gv.z + bv.z;
    o.w = (v.w - mu) * rs * gv.w + bv.w;
    ((float4*)(outf + row * Dm))[tid] = o;
    if (oh) {
        uint32_t l0, l1;
        uint32_t h0 = pack_split(o.x, o.y, l0);
        uint32_t h1 = pack_split(o.z, o.w, l1);
        *(uint2*)(oh + row * Dm + tid * 4) = make_uint2(h0, h1);
        *(uint2*)(ol + row * Dm + tid * 4) = make_uint2(l0, l1);
    }
}

// ---------------- stream/event setup at load time ----------------
struct SideStream {
    cudaStream_t s1 = nullptr;
    cudaEvent_t evFork = nullptr, evJoin = nullptr;
    bool ok = false;
    SideStream() {
        if (cudaStreamCreateWithFlags(&s1, cudaStreamNonBlocking) != cudaSuccess) return;
        if (cudaEventCreateWithFlags(&evFork, cudaEventDisableTiming) != cudaSuccess) return;
        if (cudaEventCreateWithFlags(&evJoin, cudaEventDisableTiming) != cudaSuccess) return;
        ok = true;
    }
};
static SideStream g_ss;

// ---------------- host orchestration ----------------
static inline void run_gemm(const bf16* Ah, const bf16* Al,
                            const bf16* Wh, const bf16* Wl, const float* bias,
                            float* Cf, bf16* Ch0, bf16* Cl0, bf16* Ch1, bf16* Cl1,
                            bf16* Ch2, bf16* Cl2,
                            int K, int Nmat, long long Wstride, int nTilesX,
                            int mode, int relu, bool mt128, cudaStream_t st = 0)
{
    if (mt128) {
        dim3 grid(nTilesX, MROWS / 128);
        gemm_bf<128><<<grid, 256, GP<128>::SMEM, st>>>(Ah, Al, Wh, Wl, bias, Cf,
                                                       Ch0, Cl0, Ch1, Cl1, Ch2, Cl2,
                                                       K, Nmat, Wstride, mode, relu);
    } else {
        dim3 grid(nTilesX, MROWS / 64);
        gemm_bf<64><<<grid, 256, GP<64>::SMEM, st>>>(Ah, Al, Wh, Wl, bias, Cf,
                                                     Ch0, Cl0, Ch1, Cl1, Ch2, Cl2,
                                                     K, Nmat, Wstride, mode, relu);
    }
}
static inline void run_flash(const bf16* Qh, const bf16* Ql, const bf16* Kh, const bf16* Kl,
                             const bf16* Vh, const bf16* Vl, bf16* Oh, bf16* Ol,
                             int causal, cudaStream_t st = 0)
{
    flash_kernel<<<dim3(8, Bb * Hh), 128, FA_TOTAL, st>>>(Qh, Ql, Kh, Kl, Vh, Vl, Oh, Ol, causal);
}

extern "C" void kernel_launch(void* const* d_in, const int* in_sizes, int n_in,
                              void* d_out, int out_size)
{
    static bool attrSet = false;
    if (!attrSet) {
        cudaFuncSetAttribute(gemm_bf<128>, cudaFuncAttributeMaxDynamicSharedMemorySize, GP<128>::SMEM);
        cudaFuncSetAttribute(gemm_bf<64>,  cudaFuncAttributeMaxDynamicSharedMemorySize, GP<64>::SMEM);
        cudaFuncSetAttribute(flash_kernel, cudaFuncAttributeMaxDynamicSharedMemorySize, FA_TOTAL);
        attrSet = true;
    }

    const float* src        = (const float*)d_in[0];
    const float* tgt        = (const float*)d_in[1];
    const float* enc_attn_W = (const float*)d_in[2];
    const float* enc_attn_b = (const float*)d_in[3];
    const float* enc_ffn_W1 = (const float*)d_in[4];
    const float* enc_ffn_b1 = (const float*)d_in[5];
    const float* enc_ffn_W2 = (const float*)d_in[6];
    const float* enc_ffn_b2 = (const float*)d_in[7];
    const float* enc_ln_g   = (const float*)d_in[8];
    const float* enc_ln_b   = (const float*)d_in[9];
    const float* enc_fng    = (const float*)d_in[10];
    const float* enc_fnb    = (const float*)d_in[11];
    const float* dec_sW     = (const float*)d_in[12];
    const float* dec_sb     = (const float*)d_in[13];
    const float* dec_cW     = (const float*)d_in[14];
    const float* dec_cb     = (const float*)d_in[15];
    const float* dW1        = (const float*)d_in[16];
    const float* db1        = (const float*)d_in[17];
    const float* dW2        = (const float*)d_in[18];
    const float* db2        = (const float*)d_in[19];
    const float* dec_ln_g   = (const float*)d_in[20];
    const float* dec_ln_b   = (const float*)d_in[21];
    const float* dec_fng    = (const float*)d_in[22];
    const float* dec_fnb    = (const float*)d_in[23];
    // d_in[24] = tgt_mask: exact causal tril -> applied analytically.

    float *x, *y, *mem, *tmp, *tmpd;
    cudaGetSymbolAddress((void**)&x,    g_x);
    cudaGetSymbolAddress((void**)&y,    g_y);
    cudaGetSymbolAddress((void**)&mem,  g_mem);
    cudaGetSymbolAddress((void**)&tmp,  g_tmp);
    cudaGetSymbolAddress((void**)&tmpd, g_tmpd);
    bf16 *xh,*xl,*yh,*yl,*mh,*ml,*qh,*ql,*kh,*kl,*vh,*vl,*ch,*cl,*h1h,*h1l,*whi,*wlo;
    bf16 *q2h,*q2l,*k2h,*k2l,*v2h,*v2l,*c2h,*c2l;
    cudaGetSymbolAddress((void**)&xh, g_xh);  cudaGetSymbolAddress((void**)&xl, g_xl);
    cudaGetSymbolAddress((void**)&yh, g_yh);  cudaGetSymbolAddress((void**)&yl, g_yl);
    cudaGetSymbolAddress((void**)&mh, g_mh);  cudaGetSymbolAddress((void**)&ml, g_ml);
    cudaGetSymbolAddress((void**)&qh, g_qh);  cudaGetSymbolAddress((void**)&ql, g_ql);
    cudaGetSymbolAddress((void**)&kh, g_kh);  cudaGetSymbolAddress((void**)&kl, g_kl);
    cudaGetSymbolAddress((void**)&vh, g_vh);  cudaGetSymbolAddress((void**)&vl, g_vl);
    cudaGetSymbolAddress((void**)&ch, g_ch);  cudaGetSymbolAddress((void**)&cl, g_cl);
    cudaGetSymbolAddress((void**)&h1h, g_h1h); cudaGetSymbolAddress((void**)&h1l, g_h1l);
    cudaGetSymbolAddress((void**)&whi, g_whi); cudaGetSymbolAddress((void**)&wlo, g_wlo);
    cudaGetSymbolAddress((void**)&q2h, g_q2h); cudaGetSymbolAddress((void**)&q2l, g_q2l);
    cudaGetSymbolAddress((void**)&k2h, g_k2h); cudaGetSymbolAddress((void**)&k2l, g_k2l);
    cudaGetSymbolAddress((void**)&v2h, g_v2h); cudaGetSymbolAddress((void**)&v2l, g_v2l);
    cudaGetSymbolAddress((void**)&c2h, g_c2h); cudaGetSymbolAddress((void**)&c2l, g_c2l);

    const long long DDll = (long long)DD;
    const int nPair = Bb * Ls * Dm / 2;
    const int N4 = 4 * 4 * DD / 4;

    const bool useSide = g_ss.ok;
    cudaStream_t sB = useSide ? g_ss.s1 : (cudaStream_t)0;

    // ---- fork ----
    if (useSide) {
        cudaEventRecord(g_ss.evFork, 0);
        cudaStreamWaitEvent(sB, g_ss.evFork, 0);
    }

    // ===== stream B: decoder-independent prefix =====
    wsplit<<<N4 / 256, 256, 0, sB>>>(dec_sW, whi + WOFF_DS,  wlo + WOFF_DS,  N4);
    posenc_add<<<nPair / 256, 256, 0, sB>>>(tgt, y, yh, yl);
    {
        const bf16* Wh = whi + WOFF_DS;
        const bf16* Wl = wlo + WOFF_DS;
        run_gemm(yh, yl, Wh, Wl, dec_sb, 0, q2h, q2l, k2h, k2l, v2h, v2l,
                 Dm, Dm, DDll, 12, 1, 0, true, sB);
        run_flash(q2h, q2l, k2h, k2l, v2h, v2l, c2h, c2l, 1, sB);
        run_gemm(c2h, c2l, Wh + 3 * DD, Wl + 3 * DD, dec_sb + 3 * Dm, tmpd,
                 0, 0, 0, 0, 0, 0, Dm, Dm, 0, 4, 0, 0, false, sB);
        ln_kernel<<<MROWS, 128, 0, sB>>>(y, tmpd, dec_ln_g, dec_ln_b, y, yh, yl);
    }
    wsplit<<<N4 / 256, 256, 0, sB>>>(dec_cW, whi + WOFF_DC,  wlo + WOFF_DC,  N4);
    wsplit<<<N4 / 256, 256, 0, sB>>>(dW1,    whi + WOFF_DF1, wlo + WOFF_DF1, N4);
    wsplit<<<N4 / 256, 256, 0, sB>>>(dW2,    whi + WOFF_DF2, wlo + WOFF_DF2, N4);

    // ===== stream A (default): encoder =====
    wsplit<<<N4 / 256, 256>>>(enc_attn_W, whi + WOFF_EA,  wlo + WOFF_EA,  N4);
    wsplit<<<N4 / 256, 256>>>(enc_ffn_W1, whi + WOFF_EF1, wlo + WOFF_EF1, N4);
    wsplit<<<N4 / 256, 256>>>(enc_ffn_W2, whi + WOFF_EF2, wlo + WOFF_EF2, N4);
    posenc_add<<<nPair / 256, 256>>>(src, x, xh, xl);
    for (int l = 0; l < 4; l++) {
        const bf16* Wh = whi + WOFF_EA + (size_t)l * 4 * DD;
        const bf16* Wl = wlo + WOFF_EA + (size_t)l * 4 * DD;
        const float* bb = enc_attn_b + (size_t)l * 4 * Dm;
        run_gemm(xh, xl, Wh, Wl, bb, 0, qh, ql, kh, kl, vh, vl,
                 Dm, Dm, DDll, 12, 1, 0, true);
        run_flash(qh, ql, kh, kl, vh, vl, ch, cl, 0);
        run_gemm(ch, cl, Wh + 3 * DD, Wl + 3 * DD, bb + 3 * Dm, tmp,
                 0, 0, 0, 0, 0, 0, Dm, Dm, 0, 4, 0, 0, false);
        ln_kernel<<<MROWS, 128>>>(x, tmp, enc_ln_g + (size_t)(l * 2) * Dm,
                                  enc_ln_b + (size_t)(l * 2) * Dm, x, xh, xl);
        run_gemm(xh, xl, whi + WOFF_EF1 + (size_t)l * Dm * DFF_,
                 wlo + WOFF_EF1 + (size_t)l * Dm * DFF_, enc_ffn_b1 + (size_t)l * DFF_,
                 0, h1h, h1l, 0, 0, 0, 0, Dm, DFF_, 0, 16, 2, 1, true);
        run_gemm(h1h, h1l, whi + WOFF_EF2 + (size_t)l * DFF_ * Dm,
                 wlo + WOFF_EF2 + (size_t)l * DFF_ * Dm, enc_ffn_b2 + (size_t)l * Dm,
                 tmp, 0, 0, 0, 0, 0, 0, DFF_, Dm, 0, 4, 0, 0, false);
        ln_kernel<<<MROWS, 128>>>(x, tmp, enc_ln_g + (size_t)(l * 2 + 1) * Dm,
                                  enc_ln_b + (size_t)(l * 2 + 1) * Dm, x, xh, xl);
    }
    ln_kernel<<<MROWS, 128>>>(x, nullptr, enc_fng, enc_fnb, mem, mh, ml);

    // ---- join ----
    if (useSide) {
        cudaEventRecord(g_ss.evJoin, sB);
        cudaStreamWaitEvent(0, g_ss.evJoin, 0);
    }

    // ===== decoder (layer 0 self-attn already done on stream B) =====
    for (int l = 0; l < 4; l++) {
        if (l > 0) {
            const bf16* Wh = whi + WOFF_DS + (size_t)l * 4 * DD;
            const bf16* Wl = wlo + WOFF_DS + (size_t)l * 4 * DD;
            const float* bb = dec_sb + (size_t)l * 4 * Dm;
            run_gemm(yh, yl, Wh, Wl, bb, 0, qh, ql, kh, kl, vh, vl,
                     Dm, Dm, DDll, 12, 1, 0, true);
            run_flash(qh, ql, kh, kl, vh, vl, ch, cl, 1);
            run_gemm(ch, cl, Wh + 3 * DD, Wl + 3 * DD, bb + 3 * Dm, tmp,
                     0, 0, 0, 0, 0, 0, Dm, Dm, 0, 4, 0, 0, false);
            ln_kernel<<<MROWS, 128>>>(y, tmp, dec_ln_g + (size_t)(l * 3) * Dm,
                                      dec_ln_b + (size_t)(l * 3) * Dm, y, yh, yl);
        }
        // cross-attention
        {
            const bf16* Wh = whi + WOFF_DC + (size_t)l * 4 * DD;
            const bf16* Wl = wlo + WOFF_DC + (size_t)l * 4 * DD;
            const float* bb = dec_cb + (size_t)l * 4 * Dm;
            run_gemm(yh, yl, Wh, Wl, bb, 0, qh, ql, 0, 0, 0, 0,
                     Dm, Dm, 0, 4, 1, 0, false);
            run_gemm(mh, ml, Wh + DD, Wl + DD, bb + Dm, 0, kh, kl, vh, vl, 0, 0,
                     Dm, Dm, DDll, 8, 1, 0, true);
            run_flash(qh, ql, kh, kl, vh, vl, ch, cl, 0);
            run_gemm(ch, cl, Wh + 3 * DD, Wl + 3 * DD, bb + 3 * Dm, tmp,
                     0, 0, 0, 0, 0, 0, Dm, Dm, 0, 4, 0, 0, false);
            ln_kernel<<<MROWS, 128>>>(y, tmp, dec_ln_g + (size_t)(l * 3 + 1) * Dm,
                                      dec_ln_b + (size_t)(l * 3 + 1) * Dm, y, yh, yl);
        }
        // FFN
        run_gemm(yh, yl, whi + WOFF_DF1 + (size_t)l * Dm * DFF_,
                 wlo + WOFF_DF1 + (size_t)l * Dm * DFF_, db1 + (size_t)l * DFF_,
                 0, h1h, h1l, 0, 0, 0, 0, Dm, DFF_, 0, 16, 2, 1, true);
        run_gemm(h1h, h1l, whi + WOFF_DF2 + (size_t)l * DFF_ * Dm,
                 wlo + WOFF_DF2 + (size_t)l * DFF_ * Dm, db2 + (size_t)l * Dm,
                 tmp, 0, 0, 0, 0, 0, 0, DFF_, Dm, 0, 4, 0, 0, false);
        ln_kernel<<<MROWS, 128>>>(y, tmp, dec_ln_g + (size_t)(l * 3 + 2) * Dm,
                                  dec_ln_b + (size_t)(l * 3 + 2) * Dm, y, yh, yl);
    }
    ln_kernel<<<MROWS, 128>>>(y, nullptr, dec_fng, dec_fnb, (float*)d_out, 0, 0);
}